// round 11
// baseline (speedup 1.0000x reference)
#include <cuda_runtime.h>

#define Np 1024
#define HW 4096
#define NBLK 1024       // stripe blocks
#define RPB  4          // rows per block (NBLK*RPB == HW)

// ---------------- scratch -------------------------------------------------
__device__ float    g_part[(size_t)NBLK * Np];   // 4 MB, BLK-MAJOR: [blk][box]
__device__ float    g_scores[Np];
__device__ float    g_scores_s[Np];
__device__ float    g_bbox_s[Np * 4];
__device__ unsigned g_iou[Np * 32];
__device__ unsigned g_rec_sel[Np * 32];
__device__ unsigned long long g_best;            // (scorebits<<32)|idx, 0 = none
__device__ unsigned g_sort_done, g_iou_done, g_cwsl_done;

// ---------------- K1: fused stripe scan + per-box row-interval sums --------
__global__ void k_boxsum(const float4* __restrict__ p,
                         const float* __restrict__ bbox) {
    if (blockIdx.x == 0 && threadIdx.x == 0) g_best = 0ull;  // replay reset
    __shared__ float srow[HW];
    __shared__ float swsum[8];
    int t = threadIdx.x;            // 256
    int lane = t & 31, wid = t >> 5;
    int blk = blockIdx.x;

    int bx1[4], bx2[4], by1[4], by2[4];
    double acc[4] = {0.0, 0.0, 0.0, 0.0};
#pragma unroll
    for (int k = 0; k < 4; k++) {
        int b = t + k * 256;
        float4 bb = reinterpret_cast<const float4*>(bbox)[b];
        bx1[k] = min(max((int)floorf(bb.x), 0), HW);
        by1[k] = min(max((int)floorf(bb.y), 0), HW);
        bx2[k] = min(max((int)floorf(bb.z), 0), HW);
        by2[k] = min(max((int)floorf(bb.w), 0), HW);
    }

    int y0 = blk * RPB;
#pragma unroll
    for (int r = 0; r < RPB; r++) {
        int y = y0 + r;
        const float4* pr = p + (size_t)y * (HW / 4);
        float4 v0 = pr[t * 4 + 0], v1 = pr[t * 4 + 1];
        float4 v2 = pr[t * 4 + 2], v3 = pr[t * 4 + 3];
        v0.y += v0.x; v0.z += v0.y; v0.w += v0.z;
        v1.x += v0.w; v1.y += v1.x; v1.z += v1.y; v1.w += v1.z;
        v2.x += v1.w; v2.y += v2.x; v2.z += v2.y; v2.w += v2.z;
        v3.x += v2.w; v3.y += v3.x; v3.z += v3.y; v3.w += v3.z;
        float tot = v3.w;
        float ts = tot;
#pragma unroll
        for (int o = 1; o < 32; o <<= 1) {
            float u = __shfl_up_sync(0xffffffffu, ts, o);
            if (lane >= o) ts += u;
        }
        if (lane == 31) swsum[wid] = ts;
        __syncthreads();
        float w = 0.f;
#pragma unroll
        for (int q = 0; q < 8; q++)
            if (q < wid) w += swsum[q];
        float excl = w + (ts - tot);
        v0.x += excl; v0.y += excl; v0.z += excl; v0.w += excl;
        v1.x += excl; v1.y += excl; v1.z += excl; v1.w += excl;
        v2.x += excl; v2.y += excl; v2.z += excl; v2.w += excl;
        v3.x += excl; v3.y += excl; v3.z += excl; v3.w += excl;
        float4* sr4 = reinterpret_cast<float4*>(srow);
        sr4[t * 4 + 0] = v0; sr4[t * 4 + 1] = v1;
        sr4[t * 4 + 2] = v2; sr4[t * 4 + 3] = v3;
        __syncthreads();
#pragma unroll
        for (int k = 0; k < 4; k++) {
            if (y >= by1[k] && y < by2[k]) {
                float right = (bx2[k] > 0) ? srow[bx2[k] - 1] : 0.f;
                float left  = (bx1[k] > 0) ? srow[bx1[k] - 1] : 0.f;
                acc[k] += (double)(right - left);
            }
        }
        __syncthreads();
    }
#pragma unroll
    for (int k = 0; k < 4; k++) {
        int b = t + k * 256;
        g_part[(size_t)blk * Np + b] = (float)acc[k];   // coalesced
    }
}

// ---------------- K2: transposed reduce of partials -> combined score ------
__global__ void k_boxscore(const float* __restrict__ bbox,
                           const float* __restrict__ obj) {
    if (blockIdx.x == 0 && threadIdx.x == 0) {   // reset tail sync counters
        g_sort_done = 0u; g_iou_done = 0u; g_cwsl_done = 0u;
    }
    __shared__ double sw[8][8];
    int t = threadIdx.x;            // 256
    int lane = t & 31, wid = t >> 5;
    int b0 = blockIdx.x * 8;
    int boxo = lane & 7;
    int blko = lane >> 3;
    double acc = 0.0;
    int base = wid * (NBLK / 8);
#pragma unroll 8
    for (int it = 0; it < (NBLK / 8) / 4; it++) {
        int blk = base + it * 4 + blko;
        acc += (double)g_part[(size_t)blk * Np + b0 + boxo];
    }
    acc += __shfl_down_sync(0xffffffffu, acc, 16);
    acc += __shfl_down_sync(0xffffffffu, acc, 8);
    if (lane < 8) sw[wid][lane] = acc;
    __syncthreads();
    if (t < 8) {
        double s = 0.0;
#pragma unroll
        for (int w = 0; w < 8; w++) s += sw[w][t];
        int b = b0 + t;
        float4 bb = reinterpret_cast<const float4*>(bbox)[b];
        int x1 = min(max((int)floorf(bb.x), 0), HW);
        int y1 = min(max((int)floorf(bb.y), 0), HW);
        int x2 = min(max((int)floorf(bb.z), 0), HW);
        int y2 = min(max((int)floorf(bb.w), 0), HW);
        long long cnt = (long long)(y2 - y1) * (long long)(x2 - x1);
        if (cnt < 1) cnt = 1;
        float bs = (float)(s / (double)cnt);
        g_scores[b] = 0.5f * (obj[b] + bs);
    }
}

// ---------------- K3: fused tail: sort | iou | cwsl | final -----------------
// Blocks 0..127: sort phase, then join iou. Blocks 0..2047: iou (spin on
// sort_done==128). Blocks 2048..2175: cwsl (spin on iou_done==2048; CLC
// schedules them last so spins are short). Last cwsl block emits output.
__global__ void k_tail(const float* __restrict__ bbox,
                       const int* __restrict__ counts_p,
                       float* __restrict__ out) {
    int t    = threadIdx.x;        // 256
    int lane = t & 31, wid = t >> 5;
    int bid  = blockIdx.x;

    if (bid < 2048) {
        // ---- sort phase (blocks 0..127) ----
        if (bid < 128) {
            __shared__ float ss[Np];
            for (int k = t; k < Np; k += 256) ss[k] = g_scores[k];
            __syncthreads();
            int i = bid * 8 + wid;
            float si = ss[i];
            int cnt = 0;
#pragma unroll
            for (int q = 0; q < 32; q++) {
                int j = q * 32 + lane;
                float sj = ss[j];
                cnt += (sj > si) || (sj == si && j < i);
            }
#pragma unroll
            for (int o = 16; o > 0; o >>= 1)
                cnt += __shfl_down_sync(0xffffffffu, cnt, o);
            if (lane == 0) {
                g_scores_s[cnt] = si;
                reinterpret_cast<float4*>(g_bbox_s)[cnt] =
                    reinterpret_cast<const float4*>(bbox)[i];
            }
            __syncthreads();
            if (t == 0) { __threadfence(); atomicAdd(&g_sort_done, 1u); }
        }
        // ---- wait for all sort blocks ----
        if (t == 0) {
            while (*(volatile unsigned*)&g_sort_done != 128u) { }
            __threadfence();
        }
        __syncthreads();
        // ---- iou phase (round-10 two-row mapping; 16384 warps) ----
        int g    = bid * 8 + wid;       // 0..16383
        int ip   = g >> 5;
        int word = g & 31;
        int i0   = ip * 2;
        int j    = word * 32 + lane;
        float4 c  = reinterpret_cast<const float4*>(g_bbox_s)[j];
        float4 a0 = reinterpret_cast<const float4*>(g_bbox_s)[i0];
        float4 a1 = reinterpret_cast<const float4*>(g_bbox_s)[i0 + 1];
        float carea = (c.z - c.x) * (c.w - c.y);

        float a0area = (a0.z - a0.x) * (a0.w - a0.y);
        float ix1 = fmaxf(a0.x, c.x), iy1 = fmaxf(a0.y, c.y);
        float ix2 = fminf(a0.z, c.z), iy2 = fminf(a0.w, c.w);
        float inter0 = fmaxf(ix2 - ix1, 0.f) * fmaxf(iy2 - iy1, 0.f);
        float iou0 = inter0 / (a0area + carea - inter0);
        unsigned m0 = __ballot_sync(0xffffffffu, iou0 > 0.5f);

        float a1area = (a1.z - a1.x) * (a1.w - a1.y);
        float jx1 = fmaxf(a1.x, c.x), jy1 = fmaxf(a1.y, c.y);
        float jx2 = fminf(a1.z, c.z), jy2 = fminf(a1.w, c.w);
        float inter1 = fmaxf(jx2 - jx1, 0.f) * fmaxf(jy2 - jy1, 0.f);
        float iou1 = inter1 / (a1area + carea - inter1);
        unsigned m1 = __ballot_sync(0xffffffffu, iou1 > 0.5f);

        if (lane == 0) {
            g_iou[i0 * 32 + word]       = m0;
            g_iou[(i0 + 1) * 32 + word] = m1;
        }
        __syncthreads();
        if (t == 0) { __threadfence(); atomicAdd(&g_iou_done, 1u); }
        return;
    }

    // ---- cwsl blocks (2048..2175) ----
    if (t == 0) {
        while (*(volatile unsigned*)&g_iou_done != 2048u) { }
        __threadfence();
    }
    __syncthreads();
    {
        int counts = counts_p[0];
        int i = (bid - 2048) * 8 + wid;      // 0..1023
        unsigned sel = (lane == (i >> 5)) ? (1u << (i & 31)) : 0u;
        int   size  = 1;
        float score = g_scores_s[i];
        bool  rec   = false;
        if (size == counts) {
            rec = (i < Np - 1);
        } else {
            unsigned row = (i + 1 < Np) ? g_iou[(i + 1) * 32 + lane] : 0u;
            for (int j = i + 1; j < Np; j++) {
                unsigned nxt = (j + 1 < Np) ? g_iou[(j + 1) * 32 + lane] : 0u;
                bool overlap = __any_sync(0xffffffffu, (sel & row) != 0u);
                if (!overlap) {
                    if (lane == (j >> 5)) sel |= (1u << (j & 31));
                    size++;
                    score += g_scores_s[j];
                    if (size == counts) { rec = (j < Np - 1); break; }
                }
                row = nxt;
            }
        }
        g_rec_sel[i * 32 + lane] = sel;
        if (lane == 0 && rec) {
            unsigned long long key =
                ((unsigned long long)__float_as_uint(score) << 32) | (unsigned)i;
            atomicMax(&g_best, key);
        }
    }
    __syncthreads();
    __shared__ int lastf;
    if (t == 0) {
        __threadfence();
        lastf = (atomicAdd(&g_cwsl_done, 1u) == 127u) ? 1 : 0;
    }
    __syncthreads();
    if (lastf) {
        __threadfence();
        unsigned long long key = *(volatile unsigned long long*)&g_best;
        int best = (int)(key & 0xffffffffu);
        bool any = (key != 0ull);
#pragma unroll
        for (int k = 0; k < 4; k++) {
            int idx = t + k * 256;
            unsigned bit = (g_rec_sel[best * 32 + (idx >> 5)] >> (idx & 31)) & 1u;
            out[idx] = (any && bit) ? g_scores_s[idx] : 0.f;
        }
    }
}

// ---------------- launch ----------------------------------------------------
extern "C" void kernel_launch(void* const* d_in, const int* in_sizes, int n_in,
                              void* d_out, int out_size) {
    const float* bbox   = (const float*)d_in[0];
    const float* obj    = (const float*)d_in[1];
    const float* probs  = (const float*)d_in[2];
    const int*   counts = (const int*)d_in[3];
    float* out = (float*)d_out;

    k_boxsum<<<NBLK, 256>>>((const float4*)probs, bbox);
    k_boxscore<<<Np / 8, 256>>>(bbox, obj);
    k_tail<<<2176, 256>>>(bbox, counts, out);
}

// round 12
// speedup vs baseline: 1.1491x; 1.1491x over previous
#include <cuda_runtime.h>

#define Np 1024
#define HW 4096
#define NBLK 1024       // stripe blocks
#define RPB  4          // rows per block (NBLK*RPB == HW)

// ---------------- scratch -------------------------------------------------
__device__ float    g_part[(size_t)NBLK * Np];   // 4 MB, BLK-MAJOR: [blk][box]
__device__ float    g_scores[Np];
__device__ float    g_scores_s[Np];
__device__ float    g_bbox_s[Np * 4];
__device__ unsigned g_iou[Np * 32];
__device__ unsigned g_rec_sel[Np * 32];
__device__ unsigned long long g_best;            // (scorebits<<32)|idx, 0 = none

// ---------------- K1: fused stripe scan + per-box row-interval sums --------
// 512 threads/block, 8 elems/thread, 2 boxes/thread: ~40 regs/thread ->
// 48 warps/SM (vs 24 at 72 regs). Same scan arithmetic order as before.
__global__ void k_boxsum(const float4* __restrict__ p,
                         const float* __restrict__ bbox) {
    if (blockIdx.x == 0 && threadIdx.x == 0) g_best = 0ull;  // replay reset
    __shared__ float srow[HW];      // 16 KB local scans
    __shared__ float swsum[16];
    int t = threadIdx.x;            // 512
    int lane = t & 31, wid = t >> 5;  // 16 warps
    int blk = blockIdx.x;

    int bx1[2], bx2[2], by1[2], by2[2];
    double acc[2] = {0.0, 0.0};
#pragma unroll
    for (int k = 0; k < 2; k++) {
        int b = t + k * 512;
        float4 bb = reinterpret_cast<const float4*>(bbox)[b];
        bx1[k] = min(max((int)floorf(bb.x), 0), HW);
        by1[k] = min(max((int)floorf(bb.y), 0), HW);
        bx2[k] = min(max((int)floorf(bb.z), 0), HW);
        by2[k] = min(max((int)floorf(bb.w), 0), HW);
    }

    int y0 = blk * RPB;
#pragma unroll
    for (int r = 0; r < RPB; r++) {
        int y = y0 + r;
        const float4* pr = p + (size_t)y * (HW / 4);
        float4 v0 = pr[t * 2 + 0], v1 = pr[t * 2 + 1];
        // local inclusive scan of 8 elements
        v0.y += v0.x; v0.z += v0.y; v0.w += v0.z;
        v1.x += v0.w; v1.y += v1.x; v1.z += v1.y; v1.w += v1.z;
        float tot = v1.w;
        // warp inclusive scan of per-thread totals
        float ts = tot;
#pragma unroll
        for (int o = 1; o < 32; o <<= 1) {
            float u = __shfl_up_sync(0xffffffffu, ts, o);
            if (lane >= o) ts += u;
        }
        if (lane == 31) swsum[wid] = ts;
        __syncthreads();
        float w = 0.f;
#pragma unroll
        for (int q = 0; q < 16; q++)
            if (q < wid) w += swsum[q];
        float excl = w + (ts - tot);
        v0.x += excl; v0.y += excl; v0.z += excl; v0.w += excl;
        v1.x += excl; v1.y += excl; v1.z += excl; v1.w += excl;
        float4* sr4 = reinterpret_cast<float4*>(srow);
        sr4[t * 2 + 0] = v0; sr4[t * 2 + 1] = v1;
        __syncthreads();
#pragma unroll
        for (int k = 0; k < 2; k++) {
            if (y >= by1[k] && y < by2[k]) {
                float right = (bx2[k] > 0) ? srow[bx2[k] - 1] : 0.f;
                float left  = (bx1[k] > 0) ? srow[bx1[k] - 1] : 0.f;
                acc[k] += (double)(right - left);
            }
        }
        __syncthreads();
    }
#pragma unroll
    for (int k = 0; k < 2; k++) {
        int b = t + k * 512;
        g_part[(size_t)blk * Np + b] = (float)acc[k];   // coalesced
    }
}

// ---------------- K2: transposed reduce of partials -> combined score ------
__global__ void k_boxscore(const float* __restrict__ bbox,
                           const float* __restrict__ obj) {
    __shared__ double sw[8][8];
    int t = threadIdx.x;            // 256
    int lane = t & 31, wid = t >> 5;
    int b0 = blockIdx.x * 8;
    int boxo = lane & 7;
    int blko = lane >> 3;
    double acc = 0.0;
    int base = wid * (NBLK / 8);
#pragma unroll 8
    for (int it = 0; it < (NBLK / 8) / 4; it++) {
        int blk = base + it * 4 + blko;
        acc += (double)g_part[(size_t)blk * Np + b0 + boxo];
    }
    acc += __shfl_down_sync(0xffffffffu, acc, 16);
    acc += __shfl_down_sync(0xffffffffu, acc, 8);
    if (lane < 8) sw[wid][lane] = acc;
    __syncthreads();
    if (t < 8) {
        double s = 0.0;
#pragma unroll
        for (int w = 0; w < 8; w++) s += sw[w][t];
        int b = b0 + t;
        float4 bb = reinterpret_cast<const float4*>(bbox)[b];
        int x1 = min(max((int)floorf(bb.x), 0), HW);
        int y1 = min(max((int)floorf(bb.y), 0), HW);
        int x2 = min(max((int)floorf(bb.z), 0), HW);
        int y2 = min(max((int)floorf(bb.w), 0), HW);
        long long cnt = (long long)(y2 - y1) * (long long)(x2 - x1);
        if (cnt < 1) cnt = 1;
        float bs = (float)(s / (double)cnt);
        g_scores[b] = 0.5f * (obj[b] + bs);
    }
}

// ---------------- K3: rank sort (desc score, ties asc index == stable) -----
__global__ void k_sort(const float* __restrict__ bbox) {
    __shared__ float ss[Np];
    int t = threadIdx.x;  // 256
    for (int k = t; k < Np; k += 256) ss[k] = g_scores[k];
    __syncthreads();
    int i    = blockIdx.x * 8 + (t >> 5);
    int lane = t & 31;
    float si = ss[i];
    int cnt = 0;
#pragma unroll
    for (int q = 0; q < 32; q++) {
        int j = q * 32 + lane;
        float sj = ss[j];
        cnt += (sj > si) || (sj == si && j < i);
    }
#pragma unroll
    for (int o = 16; o > 0; o >>= 1) cnt += __shfl_down_sync(0xffffffffu, cnt, o);
    if (lane == 0) {
        g_scores_s[cnt] = si;
        reinterpret_cast<float4*>(g_bbox_s)[cnt] =
            reinterpret_cast<const float4*>(bbox)[i];
    }
}

// ---------------- K4: IoU bitmask — one warp = one word for TWO rows --------
__global__ void k_iou() {
    int g    = (blockIdx.x * blockDim.x + threadIdx.x) >> 5;  // 0..16383
    int lane = threadIdx.x & 31;
    int ip   = g >> 5;            // row pair 0..511
    int word = g & 31;
    int i0   = ip * 2;
    int j    = word * 32 + lane;
    float4 c  = reinterpret_cast<const float4*>(g_bbox_s)[j];
    float4 a0 = reinterpret_cast<const float4*>(g_bbox_s)[i0];
    float4 a1 = reinterpret_cast<const float4*>(g_bbox_s)[i0 + 1];
    float carea = (c.z - c.x) * (c.w - c.y);

    float a0area = (a0.z - a0.x) * (a0.w - a0.y);
    float ix1 = fmaxf(a0.x, c.x), iy1 = fmaxf(a0.y, c.y);
    float ix2 = fminf(a0.z, c.z), iy2 = fminf(a0.w, c.w);
    float inter0 = fmaxf(ix2 - ix1, 0.f) * fmaxf(iy2 - iy1, 0.f);
    float iou0 = inter0 / (a0area + carea - inter0);
    unsigned m0 = __ballot_sync(0xffffffffu, iou0 > 0.5f);

    float a1area = (a1.z - a1.x) * (a1.w - a1.y);
    float jx1 = fmaxf(a1.x, c.x), jy1 = fmaxf(a1.y, c.y);
    float jx2 = fminf(a1.z, c.z), jy2 = fminf(a1.w, c.w);
    float inter1 = fmaxf(jx2 - jx1, 0.f) * fmaxf(jy2 - jy1, 0.f);
    float iou1 = inter1 / (a1area + carea - inter1);
    unsigned m1 = __ballot_sync(0xffffffffu, iou1 > 0.5f);

    if (lane == 0) {
        g_iou[i0 * 32 + word]       = m0;
        g_iou[(i0 + 1) * 32 + word] = m1;
    }
}

// ---------------- K5: c_wsl greedy sweep — prefetch + break-at-add ----------
__global__ void k_cwsl(const int* __restrict__ counts_p) {
    int gw   = (blockIdx.x * blockDim.x + threadIdx.x) >> 5;
    int lane = threadIdx.x & 31;
    if (gw >= Np) return;
    int counts = counts_p[0];
    int i = gw;
    unsigned sel = (lane == (i >> 5)) ? (1u << (i & 31)) : 0u;
    int   size  = 1;
    float score = g_scores_s[i];
    bool  rec   = false;
    if (size == counts) {
        rec = (i < Np - 1);
    } else {
        unsigned row = (i + 1 < Np) ? g_iou[(i + 1) * 32 + lane] : 0u;
        for (int j = i + 1; j < Np; j++) {
            unsigned nxt = (j + 1 < Np) ? g_iou[(j + 1) * 32 + lane] : 0u;
            bool overlap = __any_sync(0xffffffffu, (sel & row) != 0u);
            if (!overlap) {
                if (lane == (j >> 5)) sel |= (1u << (j & 31));
                size++;
                score += g_scores_s[j];
                if (size == counts) { rec = (j < Np - 1); break; }
            }
            row = nxt;
        }
    }
    g_rec_sel[i * 32 + lane] = sel;
    if (lane == 0 && rec) {
        unsigned long long key =
            ((unsigned long long)__float_as_uint(score) << 32) | (unsigned)i;
        atomicMax(&g_best, key);
    }
}

// ---------------- K6: decode winner + emit output ---------------------------
__global__ void k_final(float* __restrict__ out) {
    int t = threadIdx.x;
    unsigned long long key = g_best;
    int best = (int)(key & 0xffffffffu);
    bool any = (key != 0ull);
    unsigned bit = (g_rec_sel[best * 32 + (t >> 5)] >> (t & 31)) & 1u;
    out[t] = (any && bit) ? g_scores_s[t] : 0.f;
}

// ---------------- launch ----------------------------------------------------
extern "C" void kernel_launch(void* const* d_in, const int* in_sizes, int n_in,
                              void* d_out, int out_size) {
    const float* bbox   = (const float*)d_in[0];
    const float* obj    = (const float*)d_in[1];
    const float* probs  = (const float*)d_in[2];
    const int*   counts = (const int*)d_in[3];
    float* out = (float*)d_out;

    k_boxsum<<<NBLK, 512>>>((const float4*)probs, bbox);
    k_boxscore<<<Np / 8, 256>>>(bbox, obj);
    k_sort<<<Np / 8, 256>>>(bbox);
    k_iou<<<(Np / 2 * 32 * 32) / 256, 256>>>();
    k_cwsl<<<(Np * 32) / 256, 256>>>(counts);
    k_final<<<1, Np>>>(out);
}

// round 13
// speedup vs baseline: 1.3692x; 1.1915x over previous
#include <cuda_runtime.h>

#define Np 1024
#define HW 4096
#define NBLK 1024       // stripe blocks
#define RPB  4          // rows per block (NBLK*RPB == HW)

// ---------------- scratch -------------------------------------------------
__device__ float    g_part[(size_t)NBLK * Np];   // 4 MB, BLK-MAJOR: [blk][box]
__device__ float    g_scores[Np];
__device__ float    g_scores_s[Np];
__device__ float    g_bbox_s[Np * 4];
__device__ unsigned g_iou[Np * 32];
__device__ unsigned g_rec_sel[Np * 32];
__device__ unsigned long long g_best;            // (scorebits<<32)|idx, 0 = none
__device__ unsigned g_done;                      // cwsl completion counter

// ---------------- K1: stripe scan + box sums, 1 barrier/row ----------------
// 512 threads, 8 elems/thread, 2 boxes/thread, FLOAT stripe accumulators
// (validated round 8: identical rel_err; K2 reduces in double). Double-
// buffered srow: row r's store overlaps row r-1's box lookups, so only ONE
// __syncthreads per row. Buffer b is rewritten only after the barrier that
// follows its readers -> no hazard.
__global__ void k_boxsum(const float4* __restrict__ p,
                         const float* __restrict__ bbox) {
    if (blockIdx.x == 0 && threadIdx.x == 0) { g_best = 0ull; g_done = 0u; }
    __shared__ float srow[2][HW];   // 32 KB
    __shared__ float swsum[2][16];
    int t = threadIdx.x;            // 512
    int lane = t & 31, wid = t >> 5;  // 16 warps
    int blk = blockIdx.x;

    int bx1[2], bx2[2], by1[2], by2[2];
    float acc[2] = {0.f, 0.f};
#pragma unroll
    for (int k = 0; k < 2; k++) {
        int b = t + k * 512;
        float4 bb = reinterpret_cast<const float4*>(bbox)[b];
        bx1[k] = min(max((int)floorf(bb.x), 0), HW);
        by1[k] = min(max((int)floorf(bb.y), 0), HW);
        bx2[k] = min(max((int)floorf(bb.z), 0), HW);
        by2[k] = min(max((int)floorf(bb.w), 0), HW);
    }

    int y0 = blk * RPB;
#pragma unroll
    for (int r = 0; r < RPB; r++) {
        int y = y0 + r;
        const float4* pr = p + (size_t)y * (HW / 4);
        float4 v0 = pr[t * 2 + 0], v1 = pr[t * 2 + 1];
        // local inclusive scan of 8 elements
        v0.y += v0.x; v0.z += v0.y; v0.w += v0.z;
        v1.x += v0.w; v1.y += v1.x; v1.z += v1.y; v1.w += v1.z;
        float tot = v1.w;
        // warp inclusive scan of per-thread totals
        float ts = tot;
#pragma unroll
        for (int o = 1; o < 32; o <<= 1) {
            float u = __shfl_up_sync(0xffffffffu, ts, o);
            if (lane >= o) ts += u;
        }
        if (lane == 31) swsum[r & 1][wid] = ts;
        __syncthreads();          // the ONLY barrier this row
        float w = 0.f;
#pragma unroll
        for (int q = 0; q < 16; q++)
            if (q < wid) w += swsum[r & 1][q];
        float excl = w + (ts - tot);
        v0.x += excl; v0.y += excl; v0.z += excl; v0.w += excl;
        v1.x += excl; v1.y += excl; v1.z += excl; v1.w += excl;
        float4* sr4 = reinterpret_cast<float4*>(srow[r & 1]);
        sr4[t * 2 + 0] = v0; sr4[t * 2 + 1] = v1;
        // lagged lookups: row y-1 from the other buffer (completed, barriered)
        if (r > 0) {
            int yy = y - 1;
            const float* pb = srow[(r - 1) & 1];
#pragma unroll
            for (int k = 0; k < 2; k++) {
                if (yy >= by1[k] && yy < by2[k]) {
                    float right = (bx2[k] > 0) ? pb[bx2[k] - 1] : 0.f;
                    float left  = (bx1[k] > 0) ? pb[bx1[k] - 1] : 0.f;
                    acc[k] += (right - left);
                }
            }
        }
    }
    __syncthreads();
    {   // final row's lookups
        int yy = y0 + RPB - 1;
        const float* pb = srow[(RPB - 1) & 1];
#pragma unroll
        for (int k = 0; k < 2; k++) {
            if (yy >= by1[k] && yy < by2[k]) {
                float right = (bx2[k] > 0) ? pb[bx2[k] - 1] : 0.f;
                float left  = (bx1[k] > 0) ? pb[bx1[k] - 1] : 0.f;
                acc[k] += (right - left);
            }
        }
    }
#pragma unroll
    for (int k = 0; k < 2; k++) {
        int b = t + k * 512;
        g_part[(size_t)blk * Np + b] = acc[k];   // coalesced
    }
}

// ---------------- K2: transposed reduce of partials -> combined score ------
__global__ void k_boxscore(const float* __restrict__ bbox,
                           const float* __restrict__ obj) {
    __shared__ double sw[8][8];
    int t = threadIdx.x;            // 256
    int lane = t & 31, wid = t >> 5;
    int b0 = blockIdx.x * 8;
    int boxo = lane & 7;
    int blko = lane >> 3;
    double acc = 0.0;
    int base = wid * (NBLK / 8);
#pragma unroll 8
    for (int it = 0; it < (NBLK / 8) / 4; it++) {
        int blk = base + it * 4 + blko;
        acc += (double)g_part[(size_t)blk * Np + b0 + boxo];
    }
    acc += __shfl_down_sync(0xffffffffu, acc, 16);
    acc += __shfl_down_sync(0xffffffffu, acc, 8);
    if (lane < 8) sw[wid][lane] = acc;
    __syncthreads();
    if (t < 8) {
        double s = 0.0;
#pragma unroll
        for (int w = 0; w < 8; w++) s += sw[w][t];
        int b = b0 + t;
        float4 bb = reinterpret_cast<const float4*>(bbox)[b];
        int x1 = min(max((int)floorf(bb.x), 0), HW);
        int y1 = min(max((int)floorf(bb.y), 0), HW);
        int x2 = min(max((int)floorf(bb.z), 0), HW);
        int y2 = min(max((int)floorf(bb.w), 0), HW);
        long long cnt = (long long)(y2 - y1) * (long long)(x2 - x1);
        if (cnt < 1) cnt = 1;
        float bs = (float)(s / (double)cnt);
        g_scores[b] = 0.5f * (obj[b] + bs);
    }
}

// ---------------- K3: rank sort (desc score, ties asc index == stable) -----
__global__ void k_sort(const float* __restrict__ bbox) {
    __shared__ float ss[Np];
    int t = threadIdx.x;  // 256
    for (int k = t; k < Np; k += 256) ss[k] = g_scores[k];
    __syncthreads();
    int i    = blockIdx.x * 8 + (t >> 5);
    int lane = t & 31;
    float si = ss[i];
    int cnt = 0;
#pragma unroll
    for (int q = 0; q < 32; q++) {
        int j = q * 32 + lane;
        float sj = ss[j];
        cnt += (sj > si) || (sj == si && j < i);
    }
#pragma unroll
    for (int o = 16; o > 0; o >>= 1) cnt += __shfl_down_sync(0xffffffffu, cnt, o);
    if (lane == 0) {
        g_scores_s[cnt] = si;
        reinterpret_cast<float4*>(g_bbox_s)[cnt] =
            reinterpret_cast<const float4*>(bbox)[i];
    }
}

// ---------------- K4: IoU bitmask — one warp = one word for TWO rows --------
__global__ void k_iou() {
    int g    = (blockIdx.x * blockDim.x + threadIdx.x) >> 5;  // 0..16383
    int lane = threadIdx.x & 31;
    int ip   = g >> 5;            // row pair 0..511
    int word = g & 31;
    int i0   = ip * 2;
    int j    = word * 32 + lane;
    float4 c  = reinterpret_cast<const float4*>(g_bbox_s)[j];
    float4 a0 = reinterpret_cast<const float4*>(g_bbox_s)[i0];
    float4 a1 = reinterpret_cast<const float4*>(g_bbox_s)[i0 + 1];
    float carea = (c.z - c.x) * (c.w - c.y);

    float a0area = (a0.z - a0.x) * (a0.w - a0.y);
    float ix1 = fmaxf(a0.x, c.x), iy1 = fmaxf(a0.y, c.y);
    float ix2 = fminf(a0.z, c.z), iy2 = fminf(a0.w, c.w);
    float inter0 = fmaxf(ix2 - ix1, 0.f) * fmaxf(iy2 - iy1, 0.f);
    float iou0 = inter0 / (a0area + carea - inter0);
    unsigned m0 = __ballot_sync(0xffffffffu, iou0 > 0.5f);

    float a1area = (a1.z - a1.x) * (a1.w - a1.y);
    float jx1 = fmaxf(a1.x, c.x), jy1 = fmaxf(a1.y, c.y);
    float jx2 = fminf(a1.z, c.z), jy2 = fminf(a1.w, c.w);
    float inter1 = fmaxf(jx2 - jx1, 0.f) * fmaxf(jy2 - jy1, 0.f);
    float iou1 = inter1 / (a1area + carea - inter1);
    unsigned m1 = __ballot_sync(0xffffffffu, iou1 > 0.5f);

    if (lane == 0) {
        g_iou[i0 * 32 + word]       = m0;
        g_iou[(i0 + 1) * 32 + word] = m1;
    }
}

// ---------------- K5: c_wsl sweep + last-block emits output -----------------
__global__ void k_cwsl(const int* __restrict__ counts_p,
                       float* __restrict__ out) {
    int t    = threadIdx.x;        // 256 -> 128 blocks
    int lane = t & 31;
    int gw   = blockIdx.x * 8 + (t >> 5);
    int counts = counts_p[0];
    {
        int i = gw;
        unsigned sel = (lane == (i >> 5)) ? (1u << (i & 31)) : 0u;
        int   size  = 1;
        float score = g_scores_s[i];
        bool  rec   = false;
        if (size == counts) {
            rec = (i < Np - 1);
        } else {
            unsigned row = (i + 1 < Np) ? g_iou[(i + 1) * 32 + lane] : 0u;
            for (int j = i + 1; j < Np; j++) {
                unsigned nxt = (j + 1 < Np) ? g_iou[(j + 1) * 32 + lane] : 0u;
                bool overlap = __any_sync(0xffffffffu, (sel & row) != 0u);
                if (!overlap) {
                    if (lane == (j >> 5)) sel |= (1u << (j & 31));
                    size++;
                    score += g_scores_s[j];
                    if (size == counts) { rec = (j < Np - 1); break; }
                }
                row = nxt;
            }
        }
        g_rec_sel[i * 32 + lane] = sel;
        if (lane == 0 && rec) {
            unsigned long long key =
                ((unsigned long long)__float_as_uint(score) << 32) | (unsigned)i;
            atomicMax(&g_best, key);
        }
    }
    // last finishing block emits (no spinning; fence + counter)
    __syncthreads();
    __shared__ int lastf;
    if (t == 0) {
        __threadfence();
        lastf = (atomicAdd(&g_done, 1u) == 127u) ? 1 : 0;
    }
    __syncthreads();
    if (lastf) {
        __threadfence();
        unsigned long long key = *(volatile unsigned long long*)&g_best;
        int best = (int)(key & 0xffffffffu);
        bool any = (key != 0ull);
#pragma unroll
        for (int k = 0; k < 4; k++) {
            int idx = t + k * 256;
            unsigned bit = (g_rec_sel[best * 32 + (idx >> 5)] >> (idx & 31)) & 1u;
            out[idx] = (any && bit) ? g_scores_s[idx] : 0.f;
        }
    }
}

// ---------------- launch ----------------------------------------------------
extern "C" void kernel_launch(void* const* d_in, const int* in_sizes, int n_in,
                              void* d_out, int out_size) {
    const float* bbox   = (const float*)d_in[0];
    const float* obj    = (const float*)d_in[1];
    const float* probs  = (const float*)d_in[2];
    const int*   counts = (const int*)d_in[3];
    float* out = (float*)d_out;

    k_boxsum<<<NBLK, 512>>>((const float4*)probs, bbox);
    k_boxscore<<<Np / 8, 256>>>(bbox, obj);
    k_sort<<<Np / 8, 256>>>(bbox);
    k_iou<<<(Np / 2 * 32 * 32) / 256, 256>>>();
    k_cwsl<<<(Np * 32) / 256, 256>>>(counts, out);
}